// round 13
// baseline (speedup 1.0000x reference)
#include <cuda_runtime.h>
#include <cuda_bf16.h>

#define NS 2000
#define NH 64
#define NB 1024
#define NQ 4              // s-dimension split per batch pair
#define SQ (NS / NQ)      // 500 s-rows per tile
#define BG 2              // batch rows per CTA (register-blocked, concurrent)
#define NPROD 500         // producer CTAs (4 MLP rows each)
#define GRID ((NB / BG) * NQ)   // 2048

// Scratch + sync state (no cudaMalloc allowed)
__device__ float g_rel_enc[NS * NH];
__device__ int g_done = 0;     // producers completed
__device__ int g_passed = 0;   // CTAs past the gate (for replay-safe reset)

// ---------------------------------------------------------------------------
// Fused kernel.
// Phase 1 (bids 0..499): zero out, MLP 4 rows -> g_rel_enc, signal g_done.
// Gate: all 2048 CTAs spin until g_done == 500.
// Phase 2 (all): out[b,h] += sum_{s in quarter} enc[b,s,h]*rel_enc[s,h],
//   flat R11 structure, BG=2 concurrent batch rows, no barriers in hot loop.
// Last CTA through the epilogue resets counters (graph-replay determinism).
// ---------------------------------------------------------------------------
__global__ __launch_bounds__(256, 5)
void fused_kernel(const int* __restrict__ stock_idx,
                  const float* __restrict__ rel,
                  const float* __restrict__ W1,
                  const float* __restrict__ b1,
                  const float* __restrict__ W2,
                  const float* __restrict__ b2,
                  const float4* __restrict__ enc,  // [B, S, 16] float4
                  float* __restrict__ out)         // [B, 64]
{
    __shared__ float W1s[NH * 65];   // padded rows -> bank-conflict free
    __shared__ float W2s[NH * 65];
    __shared__ float rowbuf[4 * NH];
    __shared__ float hbuf[4 * NH];
    __shared__ float4 red[256];

    const int bid = blockIdx.x;
    const int t = threadIdx.x;

    // ---------------- Phase 1: producers ----------------
    if (bid < NPROD) {
        // Zero the output (bids 0..255 cover all 65536 elements)
        for (int i = bid * 256 + t; i < NB * NH; i += NPROD * 256)
            out[i] = 0.0f;

        const int r = t >> 6;      // row-within-block 0..3
        const int j = t & 63;      // hidden index 0..63
        const int idx = *stock_idx;
        const int s = bid * 4 + r;

        for (int i = t; i < NH * NH; i += 256) {
            W1s[(i >> 6) * 65 + (i & 63)] = W1[i];
            W2s[(i >> 6) * 65 + (i & 63)] = W2[i];
        }
        rowbuf[r * NH + j] = rel[(size_t)idx * NS * NH + (size_t)s * NH + j];
        __syncthreads();

        float acc = b1[j];
        #pragma unroll 16
        for (int k = 0; k < NH; k++)
            acc = fmaf(rowbuf[r * NH + k], W1s[j * 65 + k], acc);
        hbuf[r * NH + j] = fmaxf(acc, 0.0f);
        __syncthreads();

        float acc2 = b2[j];
        #pragma unroll 16
        for (int k = 0; k < NH; k++)
            acc2 = fmaf(hbuf[r * NH + k], W2s[j * 65 + k], acc2);

        if (s == idx) acc2 = 0.0f;   // exclude i == stock_idx
        g_rel_enc[s * NH + j] = acc2;

        __threadfence();             // make writes globally visible
        __syncthreads();
        if (t == 0) atomicAdd(&g_done, 1);
    }

    // ---------------- Gate ----------------
    if (t == 0) {
        volatile int* vd = &g_done;
        while (*vd < NPROD) __nanosleep(64);
        __threadfence();             // acquire
    }
    __syncthreads();

    // ---------------- Phase 2: streaming reduce (R11 hot loop) ----------------
    const int p = bid >> 2;            // batch pair 0..511
    const int q = bid & 3;             // s-quarter
    const int h16  = t & 15;           // float4 lane within hidden dim
    const int srow = t >> 4;           // 0..15

    const size_t b0 = (size_t)p * BG;
    const float4* __restrict__ enc0 = enc + (b0 * NS + (size_t)q * SQ) * 16;
    const int strideB = NS * 16;       // float4 stride between batch rows
    const float4* __restrict__ rel4 =
        ((const float4*)g_rel_enc) + (size_t)q * SQ * 16;

    float4 a0 = make_float4(0.f, 0.f, 0.f, 0.f);
    float4 a1 = a0;

    #pragma unroll 4
    for (int s = srow; s < SQ; s += 16) {
        const int o = s * 16 + h16;
        const float4 rv = rel4[o];                 // L2-resident
        const float4 e0 = __ldcs(&enc0[o]);        // stream, evict-first
        const float4 e1 = __ldcs(&enc0[o + strideB]);
        a0.x = fmaf(e0.x, rv.x, a0.x); a0.y = fmaf(e0.y, rv.y, a0.y);
        a0.z = fmaf(e0.z, rv.z, a0.z); a0.w = fmaf(e0.w, rv.w, a0.w);
        a1.x = fmaf(e1.x, rv.x, a1.x); a1.y = fmaf(e1.y, rv.y, a1.y);
        a1.z = fmaf(e1.z, rv.z, a1.z); a1.w = fmaf(e1.w, rv.w, a1.w);
    }

    float4 accs[BG] = {a0, a1};
    #pragma unroll
    for (int bi = 0; bi < BG; bi++) {
        red[t] = accs[bi];
        __syncthreads();
        #pragma unroll
        for (int off = 128; off >= 16; off >>= 1) {
            if (t < off) {
                float4 a = red[t], bb = red[t + off];
                a.x += bb.x; a.y += bb.y; a.z += bb.z; a.w += bb.w;
                red[t] = a;
            }
            __syncthreads();
        }
        if (t < 64)
            atomicAdd(&out[(b0 + bi) * NH + t], ((const float*)red)[t]);
        __syncthreads();
    }

    // ---------------- Replay-safe counter reset ----------------
    if (t == 0) {
        const int n = atomicAdd(&g_passed, 1);
        if (n == GRID - 1) {          // last CTA through: everyone passed gate
            g_done = 0;
            __threadfence();
            g_passed = 0;
        }
    }
}

// ---------------------------------------------------------------------------
// Inputs (metadata order):
//   d_in[0] stock_idx            int32   [1]
//   d_in[1] encoded_states       f32     [1024, 2000, 64]
//   d_in[2] relationship_matrix  f32     [2000, 2000, 64]
//   d_in[3] W1  f32 [64,64]   d_in[4] b1 f32 [64]
//   d_in[5] W2  f32 [64,64]   d_in[6] b2 f32 [64]
// Output: f32 [1024, 64]
// ---------------------------------------------------------------------------
extern "C" void kernel_launch(void* const* d_in, const int* in_sizes, int n_in,
                              void* d_out, int out_size)
{
    const int*   stock_idx = (const int*)  d_in[0];
    const float* enc       = (const float*)d_in[1];
    const float* rel       = (const float*)d_in[2];
    const float* W1        = (const float*)d_in[3];
    const float* b1        = (const float*)d_in[4];
    const float* W2        = (const float*)d_in[5];
    const float* b2        = (const float*)d_in[6];
    float* out = (float*)d_out;

    fused_kernel<<<GRID, 256>>>(stock_idx, rel, W1, b1, W2, b2,
                                (const float4*)enc, out);
}

// round 16
// speedup vs baseline: 1.4038x; 1.4038x over previous
#include <cuda_runtime.h>
#include <cuda_bf16.h>

#define NS 2000
#define NH 64
#define NB 1024
#define NQ 8              // s-dimension split per batch pair
#define SQ (NS / NQ)      // 250 s-rows per tile
#define BG 2              // batch rows per CTA (register-blocked, concurrent)
#define GRID ((NB / BG) * NQ)   // 4096

// Scratch for rel_encoded [S, H] (no cudaMalloc allowed)
__device__ float g_rel_enc[NS * NH];

// ---------------------------------------------------------------------------
// Kernel 1: rel_enc[s,:] = mask(s) * ( relu(rel[idx,s,:] @ W1^T + b1) @ W2^T + b2 )
// 500 blocks x 256 threads, 4 rows/block (measured fastest shape).
// Also zero-initializes out for the reduce kernel's atomics.
// ---------------------------------------------------------------------------
__global__ __launch_bounds__(256)
void mlp_kernel(const int* __restrict__ stock_idx,
                const float* __restrict__ rel,
                const float* __restrict__ W1,
                const float* __restrict__ b1,
                const float* __restrict__ W2,
                const float* __restrict__ b2,
                float* __restrict__ out)
{
    __shared__ float W1s[NH * 65];   // padded rows -> bank-conflict free
    __shared__ float W2s[NH * 65];
    __shared__ float rowbuf[4 * NH];
    __shared__ float hbuf[4 * NH];

    const int t = threadIdx.x;
    const int r = t >> 6;      // row-within-block 0..3
    const int j = t & 63;      // hidden index 0..63
    const int idx = *stock_idx;
    const int s = blockIdx.x * 4 + r;

    // Zero the output (grid-stride over 1024*64 elements)
    for (int i = blockIdx.x * 256 + t; i < NB * NH; i += gridDim.x * 256)
        out[i] = 0.0f;

    for (int i = t; i < NH * NH; i += 256) {
        W1s[(i >> 6) * 65 + (i & 63)] = W1[i];
        W2s[(i >> 6) * 65 + (i & 63)] = W2[i];
    }

    rowbuf[r * NH + j] = rel[(size_t)idx * NS * NH + (size_t)s * NH + j];
    __syncthreads();

    float acc = b1[j];
    #pragma unroll 16
    for (int k = 0; k < NH; k++)
        acc = fmaf(rowbuf[r * NH + k], W1s[j * 65 + k], acc);
    hbuf[r * NH + j] = fmaxf(acc, 0.0f);
    __syncthreads();

    float acc2 = b2[j];
    #pragma unroll 16
    for (int k = 0; k < NH; k++)
        acc2 = fmaf(hbuf[r * NH + k], W2s[j * 65 + k], acc2);

    if (s == idx) acc2 = 0.0f;   // exclude i == stock_idx
    g_rel_enc[s * NH + j] = acc2;
}

// ---------------------------------------------------------------------------
// Kernel 2: out[b,h] += sum_{s in tile} enc[b,s,h] * rel_enc[s,h]
// R11 hot loop with finer tiles: SQ=250, grid=4096 (27.7 tiles/SM ->
// last-wave tail ~3.5% instead of ~7%). BG=2 concurrent batch rows,
// no barriers / no smem in the hot loop.
// ---------------------------------------------------------------------------
__global__ __launch_bounds__(256)
void reduce_kernel(const float4* __restrict__ enc,  // [B, S, 16] float4
                   float* __restrict__ out)         // [B, 64]
{
    const int bid = blockIdx.x;
    const int p = bid >> 3;            // batch pair 0..511
    const int q = bid & 7;             // s-eighth
    const int t = threadIdx.x;
    const int h16  = t & 15;           // float4 lane within hidden dim
    const int srow = t >> 4;           // 0..15

    const size_t b0 = (size_t)p * BG;
    const float4* __restrict__ enc0 = enc + (b0 * NS + (size_t)q * SQ) * 16;
    const int strideB = NS * 16;       // float4 stride between batch rows
    const float4* __restrict__ rel4 =
        ((const float4*)g_rel_enc) + (size_t)q * SQ * 16;

    float4 a0 = make_float4(0.f, 0.f, 0.f, 0.f);
    float4 a1 = a0;

    #pragma unroll 4
    for (int s = srow; s < SQ; s += 16) {
        const int o = s * 16 + h16;
        const float4 rv = rel4[o];                 // L2-resident
        const float4 e0 = __ldcs(&enc0[o]);        // stream, evict-first
        const float4 e1 = __ldcs(&enc0[o + strideB]);
        a0.x = fmaf(e0.x, rv.x, a0.x); a0.y = fmaf(e0.y, rv.y, a0.y);
        a0.z = fmaf(e0.z, rv.z, a0.z); a0.w = fmaf(e0.w, rv.w, a0.w);
        a1.x = fmaf(e1.x, rv.x, a1.x); a1.y = fmaf(e1.y, rv.y, a1.y);
        a1.z = fmaf(e1.z, rv.z, a1.z); a1.w = fmaf(e1.w, rv.w, a1.w);
    }

    __shared__ float4 red[256];
    float4 accs[BG] = {a0, a1};

    #pragma unroll
    for (int bi = 0; bi < BG; bi++) {
        red[t] = accs[bi];
        __syncthreads();
        #pragma unroll
        for (int off = 128; off >= 16; off >>= 1) {
            if (t < off) {
                float4 a = red[t], bb = red[t + off];
                a.x += bb.x; a.y += bb.y; a.z += bb.z; a.w += bb.w;
                red[t] = a;
            }
            __syncthreads();
        }
        if (t < 64)
            atomicAdd(&out[(b0 + bi) * NH + t], ((const float*)red)[t]);
        __syncthreads();
    }
}

// ---------------------------------------------------------------------------
// Inputs (metadata order):
//   d_in[0] stock_idx            int32   [1]
//   d_in[1] encoded_states       f32     [1024, 2000, 64]
//   d_in[2] relationship_matrix  f32     [2000, 2000, 64]
//   d_in[3] W1  f32 [64,64]   d_in[4] b1 f32 [64]
//   d_in[5] W2  f32 [64,64]   d_in[6] b2 f32 [64]
// Output: f32 [1024, 64]
// ---------------------------------------------------------------------------
extern "C" void kernel_launch(void* const* d_in, const int* in_sizes, int n_in,
                              void* d_out, int out_size)
{
    const int*   stock_idx = (const int*)  d_in[0];
    const float* enc       = (const float*)d_in[1];
    const float* rel       = (const float*)d_in[2];
    const float* W1        = (const float*)d_in[3];
    const float* b1        = (const float*)d_in[4];
    const float* W2        = (const float*)d_in[5];
    const float* b2        = (const float*)d_in[6];
    float* out = (float*)d_out;

    mlp_kernel<<<NS / 4, 256>>>(stock_idx, rel, W1, b1, W2, b2, out);
    reduce_kernel<<<GRID, 256>>>((const float4*)enc, out);
}

// round 17
// speedup vs baseline: 1.4089x; 1.0036x over previous
#include <cuda_runtime.h>
#include <cuda_bf16.h>

#define NS 2000
#define NH 64
#define NB 1024
#define NQ 4              // s-dimension split per batch pair
#define SQ (NS / NQ)      // 500 s-rows per tile
#define BG 2              // batch rows per CTA (register-blocked, concurrent)
#define GRID ((NB / BG) * NQ)   // 2048

// Scratch for rel_encoded [S, H] (no cudaMalloc allowed)
__device__ float g_rel_enc[NS * NH];

// ---------------------------------------------------------------------------
// Kernel 1: rel_enc[s,:] = mask(s) * ( relu(rel[idx,s,:] @ W1^T + b1) @ W2^T + b2 )
// 500 blocks x 256 threads, 4 rows/block (measured fastest shape).
// Also zero-initializes out; triggers PDL completion at the very end.
// ---------------------------------------------------------------------------
__global__ __launch_bounds__(256)
void mlp_kernel(const int* __restrict__ stock_idx,
                const float* __restrict__ rel,
                const float* __restrict__ W1,
                const float* __restrict__ b1,
                const float* __restrict__ W2,
                const float* __restrict__ b2,
                float* __restrict__ out)
{
    __shared__ float W1s[NH * 65];   // padded rows -> bank-conflict free
    __shared__ float W2s[NH * 65];
    __shared__ float rowbuf[4 * NH];
    __shared__ float hbuf[4 * NH];

    const int t = threadIdx.x;
    const int r = t >> 6;      // row-within-block 0..3
    const int j = t & 63;      // hidden index 0..63
    const int idx = *stock_idx;
    const int s = blockIdx.x * 4 + r;

    // Zero the output (grid-stride over 1024*64 elements)
    for (int i = blockIdx.x * 256 + t; i < NB * NH; i += gridDim.x * 256)
        out[i] = 0.0f;

    for (int i = t; i < NH * NH; i += 256) {
        W1s[(i >> 6) * 65 + (i & 63)] = W1[i];
        W2s[(i >> 6) * 65 + (i & 63)] = W2[i];
    }

    rowbuf[r * NH + j] = rel[(size_t)idx * NS * NH + (size_t)s * NH + j];
    __syncthreads();

    float acc = b1[j];
    #pragma unroll 16
    for (int k = 0; k < NH; k++)
        acc = fmaf(rowbuf[r * NH + k], W1s[j * 65 + k], acc);
    hbuf[r * NH + j] = fmaxf(acc, 0.0f);
    __syncthreads();

    float acc2 = b2[j];
    #pragma unroll 16
    for (int k = 0; k < NH; k++)
        acc2 = fmaf(hbuf[r * NH + k], W2s[j * 65 + k], acc2);

    if (s == idx) acc2 = 0.0f;   // exclude i == stock_idx
    g_rel_enc[s * NH + j] = acc2;

#if __CUDA_ARCH__ >= 900
    cudaTriggerProgrammaticLaunchCompletion();
#endif
}

// ---------------------------------------------------------------------------
// Kernel 2: out[b,h] += sum_{s in quarter} enc[b,s,h] * rel_enc[s,h]
// EXACT R11 hot loop (best measured: 80.8us). PDL: launch ramps while the
// MLP tail runs; cudaGridDependencySynchronize() before any dependent read.
// ---------------------------------------------------------------------------
__global__ __launch_bounds__(256)
void reduce_kernel(const float4* __restrict__ enc,  // [B, S, 16] float4
                   float* __restrict__ out)         // [B, 64]
{
    const int tile = blockIdx.x;
    const int p = tile >> 2;           // batch pair 0..511
    const int q = tile & 3;            // s-quarter
    const int t = threadIdx.x;
    const int h16  = t & 15;           // float4 lane within hidden dim
    const int srow = t >> 4;           // 0..15

    const size_t b0 = (size_t)p * BG;
    const float4* __restrict__ enc0 = enc + (b0 * NS + (size_t)q * SQ) * 16;
    const int strideB = NS * 16;       // float4 stride between batch rows
    const float4* __restrict__ rel4 =
        ((const float4*)g_rel_enc) + (size_t)q * SQ * 16;

#if __CUDA_ARCH__ >= 900
    cudaGridDependencySynchronize();   // wait for mlp_kernel to complete
#endif

    float4 a0 = make_float4(0.f, 0.f, 0.f, 0.f);
    float4 a1 = a0;

    #pragma unroll 4
    for (int s = srow; s < SQ; s += 16) {
        const int o = s * 16 + h16;
        const float4 rv = rel4[o];                 // L2-resident
        const float4 e0 = __ldcs(&enc0[o]);        // stream, evict-first
        const float4 e1 = __ldcs(&enc0[o + strideB]);
        a0.x = fmaf(e0.x, rv.x, a0.x); a0.y = fmaf(e0.y, rv.y, a0.y);
        a0.z = fmaf(e0.z, rv.z, a0.z); a0.w = fmaf(e0.w, rv.w, a0.w);
        a1.x = fmaf(e1.x, rv.x, a1.x); a1.y = fmaf(e1.y, rv.y, a1.y);
        a1.z = fmaf(e1.z, rv.z, a1.z); a1.w = fmaf(e1.w, rv.w, a1.w);
    }

    __shared__ float4 red[256];
    float4 accs[BG] = {a0, a1};

    #pragma unroll
    for (int bi = 0; bi < BG; bi++) {
        red[t] = accs[bi];
        __syncthreads();
        #pragma unroll
        for (int off = 128; off >= 16; off >>= 1) {
            if (t < off) {
                float4 a = red[t], bb = red[t + off];
                a.x += bb.x; a.y += bb.y; a.z += bb.z; a.w += bb.w;
                red[t] = a;
            }
            __syncthreads();
        }
        if (t < 64)
            atomicAdd(&out[(b0 + bi) * NH + t], ((const float*)red)[t]);
        __syncthreads();
    }
}

// ---------------------------------------------------------------------------
// Inputs (metadata order):
//   d_in[0] stock_idx            int32   [1]
//   d_in[1] encoded_states       f32     [1024, 2000, 64]
//   d_in[2] relationship_matrix  f32     [2000, 2000, 64]
//   d_in[3] W1  f32 [64,64]   d_in[4] b1 f32 [64]
//   d_in[5] W2  f32 [64,64]   d_in[6] b2 f32 [64]
// Output: f32 [1024, 64]
// ---------------------------------------------------------------------------
extern "C" void kernel_launch(void* const* d_in, const int* in_sizes, int n_in,
                              void* d_out, int out_size)
{
    const int*   stock_idx = (const int*)  d_in[0];
    const float* enc       = (const float*)d_in[1];
    const float* rel       = (const float*)d_in[2];
    const float* W1        = (const float*)d_in[3];
    const float* b1        = (const float*)d_in[4];
    const float* W2        = (const float*)d_in[5];
    const float* b2        = (const float*)d_in[6];
    float* out = (float*)d_out;

    mlp_kernel<<<NS / 4, 256>>>(stock_idx, rel, W1, b1, W2, b2, out);

    // PDL: overlap reduce launch ramp with the MLP tail. Degrades to plain
    // serialization if the attribute is not honored — correctness-safe.
    cudaLaunchConfig_t cfg = {};
    cfg.gridDim  = dim3(GRID);
    cfg.blockDim = dim3(256);
    cfg.dynamicSmemBytes = 0;
    cfg.stream = 0;
    cudaLaunchAttribute attrs[1];
    attrs[0].id = cudaLaunchAttributeProgrammaticStreamSerialization;
    attrs[0].val.programmaticStreamSerializationAllowed = 1;
    cfg.attrs = attrs;
    cfg.numAttrs = 1;
    cudaLaunchKernelEx(&cfg, reduce_kernel, (const float4*)enc, out);
}